// round 1
// baseline (speedup 1.0000x reference)
#include <cuda_runtime.h>

#define NN 50000
#define EE 800000
#define HH 256
#define NB_SCAN 49   // ceil(NN/1024)

// ---------------- scratch (device globals; no runtime allocation) ----------------
__device__ float g_agg[(size_t)NN * HH];
__device__ float g_h1[(size_t)NN * HH];
__device__ float g_h2[(size_t)NN * HH];
__device__ float g_invdeg[NN];
__device__ int   g_deg[NN];
__device__ int   g_rowptr[NN + 1];
__device__ int   g_pos[NN];
__device__ int   g_col[EE];
__device__ int   g_bsum[NB_SCAN];

// ---------------- CSR construction ----------------
__global__ void k_zero() {
    int i = blockIdx.x * blockDim.x + threadIdx.x;
    if (i < NN) { g_deg[i] = 0; g_pos[i] = 0; }
}

__global__ void k_count(const int* __restrict__ dst) {
    int e = blockIdx.x * blockDim.x + threadIdx.x;
    if (e < EE) atomicAdd(&g_deg[dst[e]], 1);
}

__global__ void k_scan_blocks() {
    __shared__ int s[1024];
    int t = threadIdx.x;
    int i = blockIdx.x * 1024 + t;
    int v = (i < NN) ? g_deg[i] : 0;
    s[t] = v;
    __syncthreads();
    #pragma unroll
    for (int off = 1; off < 1024; off <<= 1) {
        int add = (t >= off) ? s[t - off] : 0;
        __syncthreads();
        s[t] += add;
        __syncthreads();
    }
    if (i < NN) g_rowptr[i] = s[t] - v;   // exclusive within block
    if (t == 1023) g_bsum[blockIdx.x] = s[t];
}

__global__ void k_scan_sums() {
    if (threadIdx.x == 0) {
        int run = 0;
        for (int b = 0; b < NB_SCAN; b++) { int v = g_bsum[b]; g_bsum[b] = run; run += v; }
    }
}

__global__ void k_finalize() {
    int t = threadIdx.x;
    int i = blockIdx.x * 1024 + t;
    if (i < NN) {
        g_rowptr[i] += g_bsum[blockIdx.x];
        int d = g_deg[i];
        g_invdeg[i] = 1.0f / (float)(d > 0 ? d : 1);
    }
    if (i == 0) g_rowptr[NN] = EE;
}

__global__ void k_fill(const int* __restrict__ src, const int* __restrict__ dst) {
    int e = blockIdx.x * blockDim.x + threadIdx.x;
    if (e < EE) {
        int d = dst[e];
        int p = atomicAdd(&g_pos[d], 1);
        g_col[g_rowptr[d] + p] = src[e];
    }
}

// ---------------- aggregation: one warp per destination node ----------------
__global__ void k_agg(const float* __restrict__ hin, float* __restrict__ out) {
    int gwarp = (blockIdx.x * blockDim.x + threadIdx.x) >> 5;
    int lane  = threadIdx.x & 31;
    if (gwarp >= NN) return;
    int beg = g_rowptr[gwarp], end = g_rowptr[gwarp + 1];
    float4 a0 = make_float4(0.f, 0.f, 0.f, 0.f);
    float4 a1 = make_float4(0.f, 0.f, 0.f, 0.f);
    for (int e = beg; e < end; e++) {
        const float4* r = (const float4*)(hin + (size_t)g_col[e] * HH);
        float4 v0 = __ldg(&r[lane]);
        float4 v1 = __ldg(&r[lane + 32]);
        a0.x += v0.x; a0.y += v0.y; a0.z += v0.z; a0.w += v0.w;
        a1.x += v1.x; a1.y += v1.y; a1.z += v1.z; a1.w += v1.w;
    }
    float s = g_invdeg[gwarp];
    a0.x *= s; a0.y *= s; a0.z *= s; a0.w *= s;
    a1.x *= s; a1.y *= s; a1.z *= s; a1.w *= s;
    float4* o = (float4*)(out + (size_t)gwarp * HH);
    o[lane]      = a0;
    o[lane + 32] = a1;
}

// ---------------- dual GEMM: C = act(X0 @ W0 + X1 @ W1) ----------------
// X: [M, 256] row-major, W: [256, 256] row-major. BM=128, BN=64, BK=16.
// 256 threads, thread tile 8x4.
template <int SIG>
__global__ void k_gemm_dual(const float* __restrict__ X0, const float* __restrict__ W0,
                            const float* __restrict__ X1, const float* __restrict__ W1,
                            float* __restrict__ C) {
    __shared__ float As[16][128];
    __shared__ float Bs[16][64];

    const int tid = threadIdx.x;
    const int tx = tid & 15;       // 0..15 -> N cols (4 each)
    const int ty = tid >> 4;       // 0..15 -> M rows (8 each)
    const int mBase = blockIdx.x * 128;
    const int nBase = blockIdx.y * 64;

    float acc[8][4];
    #pragma unroll
    for (int i = 0; i < 8; i++)
        #pragma unroll
        for (int j = 0; j < 4; j++) acc[i][j] = 0.f;

    #pragma unroll
    for (int phase = 0; phase < 2; phase++) {
        const float* X = phase ? X1 : X0;
        const float* W = phase ? W1 : W0;
        for (int kt = 0; kt < 256; kt += 16) {
            // load X tile -> As (transposed to [k][m]); 2 float4 per thread
            #pragma unroll
            for (int u = 0; u < 2; u++) {
                int idx4 = tid * 2 + u;            // 0..511
                int m = idx4 >> 2;                 // 0..127
                int c0 = (idx4 & 3) * 4;           // 0,4,8,12
                int grow = mBase + m;
                float4 v = make_float4(0.f, 0.f, 0.f, 0.f);
                if (grow < NN)
                    v = __ldg((const float4*)(X + (size_t)grow * 256 + kt + c0));
                As[c0 + 0][m] = v.x;
                As[c0 + 1][m] = v.y;
                As[c0 + 2][m] = v.z;
                As[c0 + 3][m] = v.w;
            }
            // load W tile -> Bs; 1 float4 per thread
            {
                int r = tid >> 4;                  // 0..15
                int c = (tid & 15) * 4;            // 0..60
                float4 v = __ldg((const float4*)(W + (size_t)(kt + r) * 256 + nBase + c));
                *((float4*)&Bs[r][c]) = v;
            }
            __syncthreads();

            #pragma unroll
            for (int kk = 0; kk < 16; kk++) {
                float4 a0 = *((const float4*)&As[kk][ty * 8]);
                float4 a1 = *((const float4*)&As[kk][ty * 8 + 4]);
                float4 b  = *((const float4*)&Bs[kk][tx * 4]);
                float a[8] = {a0.x, a0.y, a0.z, a0.w, a1.x, a1.y, a1.z, a1.w};
                float bb[4] = {b.x, b.y, b.z, b.w};
                #pragma unroll
                for (int i = 0; i < 8; i++)
                    #pragma unroll
                    for (int j = 0; j < 4; j++)
                        acc[i][j] += a[i] * bb[j];
            }
            __syncthreads();
        }
    }

    // epilogue
    #pragma unroll
    for (int i = 0; i < 8; i++) {
        int row = mBase + ty * 8 + i;
        if (row < NN) {
            float4 v;
            float vx[4];
            #pragma unroll
            for (int j = 0; j < 4; j++) {
                float c = acc[i][j];
                if (SIG) c = 1.0f / (1.0f + expf(-c));
                vx[j] = c;
            }
            v.x = vx[0]; v.y = vx[1]; v.z = vx[2]; v.w = vx[3];
            *((float4*)(C + (size_t)row * 256 + nBase + tx * 4)) = v;
        }
    }
}

// ---------------- output projection: out[n] = h[n] . Wout + b ----------------
__global__ void k_out(const float* __restrict__ h, const float* __restrict__ w,
                      const float* __restrict__ b, float* __restrict__ out) {
    int gwarp = (blockIdx.x * blockDim.x + threadIdx.x) >> 5;
    int lane  = threadIdx.x & 31;
    if (gwarp >= NN) return;
    const float4* hr = (const float4*)(h + (size_t)gwarp * HH);
    const float4* wr = (const float4*)w;
    float4 h0 = __ldg(&hr[lane]),     w0 = __ldg(&wr[lane]);
    float4 h1 = __ldg(&hr[lane + 32]), w1 = __ldg(&wr[lane + 32]);
    float s = h0.x * w0.x + h0.y * w0.y + h0.z * w0.z + h0.w * w0.w
            + h1.x * w1.x + h1.y * w1.y + h1.z * w1.z + h1.w * w1.w;
    #pragma unroll
    for (int off = 16; off > 0; off >>= 1)
        s += __shfl_xor_sync(0xFFFFFFFF, s, off);
    if (lane == 0) out[gwarp] = s + b[0];
}

extern "C" void kernel_launch(void* const* d_in, const int* in_sizes, int n_in,
                              void* d_out, int out_size) {
    const float* x      = (const float*)d_in[0];
    const int*   ei     = (const int*)d_in[1];   // [2, E]: src = ei, dst = ei+E
    const float* WA_in  = (const float*)d_in[2];
    const float* WB_in  = (const float*)d_in[3];
    const float* A_st   = (const float*)d_in[4]; // [2, 256, 256]
    const float* B_st   = (const float*)d_in[5];
    const float* W_out  = (const float*)d_in[6];
    const float* b_out  = (const float*)d_in[7];
    float*       out    = (float*)d_out;

    const int* src = ei;
    const int* dst = ei + EE;

    float* agg; cudaGetSymbolAddress((void**)&agg, g_agg);
    float* h1;  cudaGetSymbolAddress((void**)&h1, g_h1);
    float* h2;  cudaGetSymbolAddress((void**)&h2, g_h2);

    // CSR build
    k_zero<<<(NN + 255) / 256, 256>>>();
    k_count<<<(EE + 255) / 256, 256>>>(dst);
    k_scan_blocks<<<NB_SCAN, 1024>>>();
    k_scan_sums<<<1, 32>>>();
    k_finalize<<<NB_SCAN, 1024>>>();
    k_fill<<<(EE + 255) / 256, 256>>>(src, dst);

    dim3 gGemm((NN + 127) / 128, 4);
    const int aggBlocks = (NN + 7) / 8;  // 8 warps/block

    // layer 0: h1 = mean_agg(x) @ WA_in + x @ WB_in
    k_agg<<<aggBlocks, 256>>>(x, agg);
    k_gemm_dual<0><<<gGemm, 256>>>(agg, WA_in, x, WB_in, h1);

    // layer 1: h2 = sigmoid(mean_agg(h1) @ A0 + h1 @ B0)
    k_agg<<<aggBlocks, 256>>>(h1, agg);
    k_gemm_dual<1><<<gGemm, 256>>>(agg, A_st, h1, B_st, h2);

    // layer 2: h1 = sigmoid(mean_agg(h2) @ A1 + h2 @ B1)
    k_agg<<<aggBlocks, 256>>>(h2, agg);
    k_gemm_dual<1><<<gGemm, 256>>>(agg, A_st + 256 * 256, h2, B_st + 256 * 256, h1);

    // projection
    k_out<<<aggBlocks, 256>>>(h1, W_out, b_out, out);
}

// round 3
// speedup vs baseline: 1.3520x; 1.3520x over previous
#include <cuda_runtime.h>
#include <cuda_bf16.h>
#include <mma.h>
#include <cstdint>

using namespace nvcuda;

#define NN 50000
#define EE 800000
#define HH 256
#define NB_SCAN 49   // ceil(NN/1024)

// ---------------- scratch (device globals; no runtime allocation) ----------------
__device__ float g_h1[(size_t)NN * HH];
__device__ float g_h2[(size_t)NN * HH];
__device__ __nv_bfloat16 g_agg_hi[(size_t)NN * HH];
__device__ __nv_bfloat16 g_agg_lo[(size_t)NN * HH];
__device__ __nv_bfloat16 g_x_hi[(size_t)NN * HH];
__device__ __nv_bfloat16 g_x_lo[(size_t)NN * HH];
__device__ __nv_bfloat16 g_ha_hi[(size_t)NN * HH];
__device__ __nv_bfloat16 g_ha_lo[(size_t)NN * HH];
__device__ __nv_bfloat16 g_hb_hi[(size_t)NN * HH];
__device__ __nv_bfloat16 g_hb_lo[(size_t)NN * HH];
__device__ __nv_bfloat16 g_w_hi[6 * HH * HH];
__device__ __nv_bfloat16 g_w_lo[6 * HH * HH];
__device__ float g_invdeg[NN];
__device__ int   g_deg[NN];
__device__ int   g_rowptr[NN + 1];
__device__ int   g_pos[NN];
__device__ int   g_col[EE];
__device__ int   g_bsum[NB_SCAN];

// ---------------- bf16 split helper ----------------
__device__ __forceinline__ void split_store4(float4 v, __nv_bfloat16* hi, __nv_bfloat16* lo) {
    __nv_bfloat16 h0 = __float2bfloat16(v.x), h1 = __float2bfloat16(v.y);
    __nv_bfloat16 h2 = __float2bfloat16(v.z), h3 = __float2bfloat16(v.w);
    __nv_bfloat16 l0 = __float2bfloat16(v.x - __bfloat162float(h0));
    __nv_bfloat16 l1 = __float2bfloat16(v.y - __bfloat162float(h1));
    __nv_bfloat16 l2 = __float2bfloat16(v.z - __bfloat162float(h2));
    __nv_bfloat16 l3 = __float2bfloat16(v.w - __bfloat162float(h3));
    uint2 H, L;
    H.x = ((uint32_t)__bfloat16_as_ushort(h1) << 16) | __bfloat16_as_ushort(h0);
    H.y = ((uint32_t)__bfloat16_as_ushort(h3) << 16) | __bfloat16_as_ushort(h2);
    L.x = ((uint32_t)__bfloat16_as_ushort(l1) << 16) | __bfloat16_as_ushort(l0);
    L.y = ((uint32_t)__bfloat16_as_ushort(l3) << 16) | __bfloat16_as_ushort(l2);
    *(uint2*)hi = H;
    *(uint2*)lo = L;
}

// ---------------- CSR construction ----------------
__global__ void k_zero() {
    int i = blockIdx.x * blockDim.x + threadIdx.x;
    if (i < NN) { g_deg[i] = 0; g_pos[i] = 0; }
}

__global__ void k_count(const int* __restrict__ dst) {
    int e = blockIdx.x * blockDim.x + threadIdx.x;
    if (e < EE) atomicAdd(&g_deg[dst[e]], 1);
}

__global__ void k_scan_blocks() {
    __shared__ int s[1024];
    int t = threadIdx.x;
    int i = blockIdx.x * 1024 + t;
    int v = (i < NN) ? g_deg[i] : 0;
    s[t] = v;
    __syncthreads();
    #pragma unroll
    for (int off = 1; off < 1024; off <<= 1) {
        int add = (t >= off) ? s[t - off] : 0;
        __syncthreads();
        s[t] += add;
        __syncthreads();
    }
    if (i < NN) g_rowptr[i] = s[t] - v;
    if (t == 1023) g_bsum[blockIdx.x] = s[t];
}

__global__ void k_scan_sums() {
    __shared__ int s[64];
    int t = threadIdx.x;
    int v = (t < NB_SCAN) ? g_bsum[t] : 0;
    s[t] = v;
    __syncthreads();
    #pragma unroll
    for (int off = 1; off < 64; off <<= 1) {
        int a = (t >= off) ? s[t - off] : 0;
        __syncthreads();
        s[t] += a;
        __syncthreads();
    }
    if (t < NB_SCAN) g_bsum[t] = s[t] - v;
}

__global__ void k_finalize() {
    int t = threadIdx.x;
    int i = blockIdx.x * 1024 + t;
    if (i < NN) {
        g_rowptr[i] += g_bsum[blockIdx.x];
        int d = g_deg[i];
        g_invdeg[i] = 1.0f / (float)(d > 0 ? d : 1);
    }
    if (i == 0) g_rowptr[NN] = EE;
}

__global__ void k_fill(const int* __restrict__ src, const int* __restrict__ dst) {
    int e = blockIdx.x * blockDim.x + threadIdx.x;
    if (e < EE) {
        int d = dst[e];
        int p = atomicAdd(&g_pos[d], 1);
        g_col[g_rowptr[d] + p] = src[e];
    }
}

// ---------------- weight conversion: transpose [K,N]->[N,K] + bf16 hi/lo split ----------------
__global__ void k_convert_w(const float* __restrict__ WA, const float* __restrict__ WB,
                            const float* __restrict__ Ast, const float* __restrict__ Bst) {
    int mat = blockIdx.y;
    const float* W = (mat == 0) ? WA : (mat == 1) ? WB : (mat == 2) ? Ast :
                     (mat == 3) ? Bst : (mat == 4) ? (Ast + HH * HH) : (Bst + HH * HH);
    int idx = blockIdx.x * blockDim.x + threadIdx.x;
    if (idx >= HH * HH) return;
    int k = idx >> 8, n = idx & 255;
    float v = __ldg(W + idx);                  // W[k][n]
    __nv_bfloat16 h = __float2bfloat16(v);
    __nv_bfloat16 l = __float2bfloat16(v - __bfloat162float(h));
    size_t o = (size_t)mat * HH * HH + (size_t)n * HH + k;
    g_w_hi[o] = h;
    g_w_lo[o] = l;
}

// ---------------- aggregation: one warp per dst node; fused hi/lo split of agg AND self row ----------------
__global__ void k_agg(const float* __restrict__ hin,
                      __nv_bfloat16* __restrict__ s_hi, __nv_bfloat16* __restrict__ s_lo) {
    int gwarp = (blockIdx.x * blockDim.x + threadIdx.x) >> 5;
    int lane  = threadIdx.x & 31;
    if (gwarp >= NN) return;
    int beg = g_rowptr[gwarp], end = g_rowptr[gwarp + 1];
    float4 a0 = make_float4(0.f, 0.f, 0.f, 0.f);
    float4 a1 = make_float4(0.f, 0.f, 0.f, 0.f);
    for (int e = beg; e < end; e++) {
        const float4* r = (const float4*)(hin + (size_t)g_col[e] * HH);
        float4 v0 = __ldg(&r[lane]);
        float4 v1 = __ldg(&r[lane + 32]);
        a0.x += v0.x; a0.y += v0.y; a0.z += v0.z; a0.w += v0.w;
        a1.x += v1.x; a1.y += v1.y; a1.z += v1.z; a1.w += v1.w;
    }
    float s = g_invdeg[gwarp];
    a0.x *= s; a0.y *= s; a0.z *= s; a0.w *= s;
    a1.x *= s; a1.y *= s; a1.z *= s; a1.w *= s;
    size_t base = (size_t)gwarp * HH;
    split_store4(a0, g_agg_hi + base + lane * 4,       g_agg_lo + base + lane * 4);
    split_store4(a1, g_agg_hi + base + 128 + lane * 4, g_agg_lo + base + 128 + lane * 4);
    // fused self-path split
    const float4* own = (const float4*)(hin + base);
    float4 o0 = __ldg(&own[lane]);
    float4 o1 = __ldg(&own[lane + 32]);
    split_store4(o0, s_hi + base + lane * 4,       s_lo + base + lane * 4);
    split_store4(o1, s_hi + base + 128 + lane * 4, s_lo + base + 128 + lane * 4);
}

// ---------------- wmma bf16 dual GEMM with split precision ----------------
// C[128,128] tile = act( sum over 6 segments Aseg[128,256] @ Bseg[256,256-slice] )
// Segments: Xa_hi*Wa_hi + Xa_lo*Wa_hi + Xa_hi*Wa_lo + Xs_hi*Wb_hi + Xs_lo*Wb_hi + Xs_hi*Wb_lo
#define PAD 40        // SMEM row stride in elements (80B: 16B-aligned + conflict-free ldmatrix)
#define NSTAGE 48     // 6 segments * (256/32) k-chunks

__global__ void __launch_bounds__(256) k_gemm_wmma(
    const __nv_bfloat16* __restrict__ Xa_hi, const __nv_bfloat16* __restrict__ Xa_lo,
    const __nv_bfloat16* __restrict__ Xs_hi, const __nv_bfloat16* __restrict__ Xs_lo,
    const __nv_bfloat16* __restrict__ Wa_hi, const __nv_bfloat16* __restrict__ Wa_lo,
    const __nv_bfloat16* __restrict__ Wb_hi, const __nv_bfloat16* __restrict__ Wb_lo,
    float* __restrict__ Hout, int sig)
{
    __shared__ __nv_bfloat16 smA[2][128 * PAD];
    __shared__ __nv_bfloat16 smB[2][128 * PAD];

    const int tid = threadIdx.x;
    const int wid = tid >> 5;
    const int wm = wid >> 1;      // 0..3 -> 32-row band
    const int wn = wid & 1;       // 0..1 -> 64-col band
    const int r0 = blockIdx.x * 128;
    const int n0 = blockIdx.y * 128;

    const __nv_bfloat16* Aseg[6] = { Xa_hi, Xa_lo, Xa_hi, Xs_hi, Xs_lo, Xs_hi };
    const __nv_bfloat16* Bseg[6] = { Wa_hi, Wa_hi, Wa_lo, Wb_hi, Wb_hi, Wb_lo };

    wmma::fragment<wmma::accumulator, 16, 16, 16, float> acc[2][4];
    #pragma unroll
    for (int i = 0; i < 2; i++)
        #pragma unroll
        for (int j = 0; j < 4; j++)
            wmma::fill_fragment(acc[i][j], 0.0f);

    const int c0 = tid * 2;       // two 16B chunks per thread per tile
    const int rowL = c0 >> 2, kqL = c0 & 3;
    const int c1 = c0 + 1;
    const int rowH = c1 >> 2, kqH = c1 & 3;

    // ---- stage loader (cp.async) ----
    auto load_stage = [&](int s) {
        int buf = s & 1;
        int seg = s >> 3;
        int kc  = (s & 7) * 32;
        const __nv_bfloat16* Ap = Aseg[seg];
        const __nv_bfloat16* Bp = Bseg[seg];
        // chunk 0
        {
            int node = r0 + rowL;
            const void* ga = Ap + (size_t)(node < NN ? node : 0) * HH + kc + kqL * 8;
            uint32_t da = (uint32_t)__cvta_generic_to_shared(&smA[buf][rowL * PAD + kqL * 8]);
            int sz = (node < NN) ? 16 : 0;
            asm volatile("cp.async.cg.shared.global [%0], [%1], 16, %2;" :: "r"(da), "l"(ga), "r"(sz) : "memory");
            const void* gb = Bp + (size_t)(n0 + rowL) * HH + kc + kqL * 8;
            uint32_t db = (uint32_t)__cvta_generic_to_shared(&smB[buf][rowL * PAD + kqL * 8]);
            asm volatile("cp.async.cg.shared.global [%0], [%1], 16;" :: "r"(db), "l"(gb) : "memory");
        }
        // chunk 1
        {
            int node = r0 + rowH;
            const void* ga = Ap + (size_t)(node < NN ? node : 0) * HH + kc + kqH * 8;
            uint32_t da = (uint32_t)__cvta_generic_to_shared(&smA[buf][rowH * PAD + kqH * 8]);
            int sz = (node < NN) ? 16 : 0;
            asm volatile("cp.async.cg.shared.global [%0], [%1], 16, %2;" :: "r"(da), "l"(ga), "r"(sz) : "memory");
            const void* gb = Bp + (size_t)(n0 + rowH) * HH + kc + kqH * 8;
            uint32_t db = (uint32_t)__cvta_generic_to_shared(&smB[buf][rowH * PAD + kqH * 8]);
            asm volatile("cp.async.cg.shared.global [%0], [%1], 16;" :: "r"(db), "l"(gb) : "memory");
        }
        asm volatile("cp.async.commit_group;" ::: "memory");
    };

    load_stage(0);

    for (int s = 0; s < NSTAGE; s++) {
        asm volatile("cp.async.wait_group 0;" ::: "memory");
        __syncthreads();
        int buf = s & 1;
        if (s + 1 < NSTAGE) load_stage(s + 1);

        #pragma unroll
        for (int kk = 0; kk < 32; kk += 16) {
            wmma::fragment<wmma::matrix_a, 16, 16, 16, __nv_bfloat16, wmma::row_major> af[2];
            wmma::fragment<wmma::matrix_b, 16, 16, 16, __nv_bfloat16, wmma::col_major> bf[4];
            #pragma unroll
            for (int i = 0; i < 2; i++)
                wmma::load_matrix_sync(af[i], &smA[buf][(wm * 32 + i * 16) * PAD + kk], PAD);
            #pragma unroll
            for (int j = 0; j < 4; j++)
                wmma::load_matrix_sync(bf[j], &smB[buf][(wn * 64 + j * 16) * PAD + kk], PAD);
            #pragma unroll
            for (int i = 0; i < 2; i++)
                #pragma unroll
                for (int j = 0; j < 4; j++)
                    wmma::mma_sync(acc[i][j], af[i], bf[j], acc[i][j]);
        }
    }

    // epilogue: optional sigmoid, store fp32 (NN % 16 == 0 so 16-row tiles never straddle)
    #pragma unroll
    for (int i = 0; i < 2; i++) {
        int mrow = r0 + wm * 32 + i * 16;
        if (mrow < NN) {
            #pragma unroll
            for (int j = 0; j < 4; j++) {
                if (sig) {
                    #pragma unroll
                    for (int e = 0; e < acc[i][j].num_elements; e++)
                        acc[i][j].x[e] = 1.0f / (1.0f + expf(-acc[i][j].x[e]));
                }
                wmma::store_matrix_sync(Hout + (size_t)mrow * HH + n0 + wn * 64 + j * 16,
                                        acc[i][j], HH, wmma::mem_row_major);
            }
        }
    }
}

// ---------------- output projection ----------------
__global__ void k_out(const float* __restrict__ h, const float* __restrict__ w,
                      const float* __restrict__ b, float* __restrict__ out) {
    int gwarp = (blockIdx.x * blockDim.x + threadIdx.x) >> 5;
    int lane  = threadIdx.x & 31;
    if (gwarp >= NN) return;
    const float4* hr = (const float4*)(h + (size_t)gwarp * HH);
    const float4* wr = (const float4*)w;
    float4 h0 = __ldg(&hr[lane]),      w0 = __ldg(&wr[lane]);
    float4 h1 = __ldg(&hr[lane + 32]), w1 = __ldg(&wr[lane + 32]);
    float s = h0.x * w0.x + h0.y * w0.y + h0.z * w0.z + h0.w * w0.w
            + h1.x * w1.x + h1.y * w1.y + h1.z * w1.z + h1.w * w1.w;
    #pragma unroll
    for (int off = 16; off > 0; off >>= 1)
        s += __shfl_xor_sync(0xFFFFFFFF, s, off);
    if (lane == 0) out[gwarp] = s + b[0];
}

extern "C" void kernel_launch(void* const* d_in, const int* in_sizes, int n_in,
                              void* d_out, int out_size) {
    const float* x     = (const float*)d_in[0];
    const int*   ei    = (const int*)d_in[1];
    const float* WA_in = (const float*)d_in[2];
    const float* WB_in = (const float*)d_in[3];
    const float* A_st  = (const float*)d_in[4];
    const float* B_st  = (const float*)d_in[5];
    const float* W_out = (const float*)d_in[6];
    const float* b_out = (const float*)d_in[7];
    float*       out   = (float*)d_out;

    const int* src = ei;
    const int* dst = ei + EE;

    float* h1; cudaGetSymbolAddress((void**)&h1, g_h1);
    float* h2; cudaGetSymbolAddress((void**)&h2, g_h2);
    __nv_bfloat16 *agg_hi, *agg_lo, *x_hi, *x_lo, *ha_hi, *ha_lo, *hb_hi, *hb_lo, *w_hi, *w_lo;
    cudaGetSymbolAddress((void**)&agg_hi, g_agg_hi);
    cudaGetSymbolAddress((void**)&agg_lo, g_agg_lo);
    cudaGetSymbolAddress((void**)&x_hi, g_x_hi);
    cudaGetSymbolAddress((void**)&x_lo, g_x_lo);
    cudaGetSymbolAddress((void**)&ha_hi, g_ha_hi);
    cudaGetSymbolAddress((void**)&ha_lo, g_ha_lo);
    cudaGetSymbolAddress((void**)&hb_hi, g_hb_hi);
    cudaGetSymbolAddress((void**)&hb_lo, g_hb_lo);
    cudaGetSymbolAddress((void**)&w_hi, g_w_hi);
    cudaGetSymbolAddress((void**)&w_lo, g_w_lo);

    // CSR build
    k_zero<<<(NN + 255) / 256, 256>>>();
    k_count<<<(EE + 255) / 256, 256>>>(dst);
    k_scan_blocks<<<NB_SCAN, 1024>>>();
    k_scan_sums<<<1, 64>>>();
    k_finalize<<<NB_SCAN, 1024>>>();
    k_fill<<<(EE + 255) / 256, 256>>>(src, dst);

    // weight conversion (transpose + bf16 hi/lo split), all 6 mats in one launch
    dim3 gW((HH * HH + 255) / 256, 6);
    k_convert_w<<<gW, 256>>>(WA_in, WB_in, A_st, B_st);

    const int aggBlocks = (NN + 7) / 8;
    dim3 gGemm((NN + 127) / 128, 2);
    const size_t WSZ = (size_t)HH * HH;

    // layer 0: h1 = agg(x)@WA + x@WB   (k_agg also produces x hi/lo self split)
    k_agg<<<aggBlocks, 256>>>(x, x_hi, x_lo);
    k_gemm_wmma<<<gGemm, 256>>>(agg_hi, agg_lo, x_hi, x_lo,
        w_hi + 0 * WSZ, w_lo + 0 * WSZ, w_hi + 1 * WSZ, w_lo + 1 * WSZ, h1, 0);

    // layer 1: h2 = sigmoid(agg(h1)@A0 + h1@B0)
    k_agg<<<aggBlocks, 256>>>(h1, ha_hi, ha_lo);
    k_gemm_wmma<<<gGemm, 256>>>(agg_hi, agg_lo, ha_hi, ha_lo,
        w_hi + 2 * WSZ, w_lo + 2 * WSZ, w_hi + 3 * WSZ, w_lo + 3 * WSZ, h2, 1);

    // layer 2: h1 = sigmoid(agg(h2)@A1 + h2@B1)
    k_agg<<<aggBlocks, 256>>>(h2, hb_hi, hb_lo);
    k_gemm_wmma<<<gGemm, 256>>>(agg_hi, agg_lo, hb_hi, hb_lo,
        w_hi + 4 * WSZ, w_lo + 4 * WSZ, w_hi + 5 * WSZ, w_lo + 5 * WSZ, h1, 1);

    // projection
    k_out<<<aggBlocks, 256>>>(h1, W_out, b_out, out);
}

// round 4
// speedup vs baseline: 1.8184x; 1.3450x over previous
#include <cuda_runtime.h>
#include <cuda_bf16.h>
#include <cuda_fp16.h>
#include <mma.h>
#include <cstdint>

using namespace nvcuda;

#define NN 50000
#define EE 800000
#define HH 256
#define NB_SCAN 49   // ceil(NN/1024)

// ---------------- scratch (device globals; no runtime allocation) ----------------
__device__ __nv_bfloat16 g_x_hi[(size_t)NN * HH];
__device__ __nv_bfloat16 g_x_lo[(size_t)NN * HH];
__device__ __nv_bfloat16 g_h_hi[(size_t)NN * HH];
__device__ __nv_bfloat16 g_h_lo[(size_t)NN * HH];
__device__ __half        g_P[(size_t)NN * HH];
__device__ float         g_S[(size_t)NN * HH];
__device__ float         g_h3[(size_t)NN * HH];
__device__ __nv_bfloat16 g_wcat_hi[3 * 512 * HH];
__device__ __nv_bfloat16 g_wcat_lo[3 * 512 * HH];
__device__ float g_invdeg[NN];
__device__ int   g_deg[NN];
__device__ int   g_rowptr[NN + 1];
__device__ int   g_pos[NN];
__device__ int   g_col[EE];
__device__ int   g_bsum[NB_SCAN];

// ---------------- bf16 split helper ----------------
__device__ __forceinline__ void split8(const float* v, __nv_bfloat16* hi, __nv_bfloat16* lo) {
    uint4 H, L;
    uint32_t* Hp = (uint32_t*)&H;
    uint32_t* Lp = (uint32_t*)&L;
    #pragma unroll
    for (int p = 0; p < 4; p++) {
        __nv_bfloat16 h0 = __float2bfloat16(v[p * 2 + 0]);
        __nv_bfloat16 h1 = __float2bfloat16(v[p * 2 + 1]);
        __nv_bfloat16 l0 = __float2bfloat16(v[p * 2 + 0] - __bfloat162float(h0));
        __nv_bfloat16 l1 = __float2bfloat16(v[p * 2 + 1] - __bfloat162float(h1));
        Hp[p] = ((uint32_t)__bfloat16_as_ushort(h1) << 16) | __bfloat16_as_ushort(h0);
        Lp[p] = ((uint32_t)__bfloat16_as_ushort(l1) << 16) | __bfloat16_as_ushort(l0);
    }
    *(uint4*)hi = H;
    *(uint4*)lo = L;
}

// ---------------- CSR construction ----------------
__global__ void k_zero() {
    int i = blockIdx.x * blockDim.x + threadIdx.x;
    if (i < NN) { g_deg[i] = 0; g_pos[i] = 0; }
}

__global__ void k_count(const int* __restrict__ dst) {
    int e = blockIdx.x * blockDim.x + threadIdx.x;
    if (e < EE) atomicAdd(&g_deg[dst[e]], 1);
}

__global__ void k_scan_blocks() {
    __shared__ int s[1024];
    int t = threadIdx.x;
    int i = blockIdx.x * 1024 + t;
    int v = (i < NN) ? g_deg[i] : 0;
    s[t] = v;
    __syncthreads();
    #pragma unroll
    for (int off = 1; off < 1024; off <<= 1) {
        int add = (t >= off) ? s[t - off] : 0;
        __syncthreads();
        s[t] += add;
        __syncthreads();
    }
    if (i < NN) g_rowptr[i] = s[t] - v;
    if (t == 1023) g_bsum[blockIdx.x] = s[t];
}

__global__ void k_scan_sums() {
    __shared__ int s[64];
    int t = threadIdx.x;
    int v = (t < NB_SCAN) ? g_bsum[t] : 0;
    s[t] = v;
    __syncthreads();
    #pragma unroll
    for (int off = 1; off < 64; off <<= 1) {
        int a = (t >= off) ? s[t - off] : 0;
        __syncthreads();
        s[t] += a;
        __syncthreads();
    }
    if (t < NB_SCAN) g_bsum[t] = s[t] - v;
}

__global__ void k_finalize() {
    int t = threadIdx.x;
    int i = blockIdx.x * 1024 + t;
    if (i < NN) {
        g_rowptr[i] += g_bsum[blockIdx.x];
        int d = g_deg[i];
        g_invdeg[i] = 1.0f / (float)(d > 0 ? d : 1);
    }
    if (i == 0) g_rowptr[NN] = EE;
}

__global__ void k_fill(const int* __restrict__ src, const int* __restrict__ dst) {
    int e = blockIdx.x * blockDim.x + threadIdx.x;
    if (e < EE) {
        int d = dst[e];
        int p = atomicAdd(&g_pos[d], 1);
        g_col[g_rowptr[d] + p] = src[e];
    }
}

// ---------------- weight conversion: concat [Wagg|Wself], transpose to [512,256], bf16 split ----------------
__global__ void k_convert_w(const float* __restrict__ WA, const float* __restrict__ WB,
                            const float* __restrict__ Ast, const float* __restrict__ Bst) {
    int l = blockIdx.y;
    const float* Wagg  = (l == 0) ? WA : (l == 1) ? Ast : (Ast + HH * HH);
    const float* Wself = (l == 0) ? WB : (l == 1) ? Bst : (Bst + HH * HH);
    int idx = blockIdx.x * blockDim.x + threadIdx.x;   // 0 .. 512*256-1
    if (idx >= 512 * HH) return;
    int n = idx >> 8, k = idx & 255;
    const float* srcW = (n < 256) ? Wagg : Wself;
    float v = __ldg(srcW + k * HH + (n & 255));
    __nv_bfloat16 h = __float2bfloat16(v);
    __nv_bfloat16 lo = __float2bfloat16(v - __bfloat162float(h));
    size_t o = (size_t)l * 512 * HH + idx;
    g_wcat_hi[o] = h;
    g_wcat_lo[o] = lo;
}

// ---------------- input split ----------------
__global__ void k_split_x(const float* __restrict__ x) {
    int i = blockIdx.x * blockDim.x + threadIdx.x;   // group of 8 floats
    if (i >= NN * HH / 8) return;
    float v[8];
    const float4* p = (const float4*)x + i * 2;
    float4 a = __ldg(p), b = __ldg(p + 1);
    v[0] = a.x; v[1] = a.y; v[2] = a.z; v[3] = a.w;
    v[4] = b.x; v[5] = b.y; v[6] = b.z; v[7] = b.w;
    split8(v, g_x_hi + (size_t)i * 8, g_x_lo + (size_t)i * 8);
}

// ---------------- wmma split GEMM: [P|S] = Xsplit @ Wcat ----------------
// acc = Xhi@Whi + Xlo@Whi + Xhi@Wlo ; 8 k-chunks of 32; 4 tiles/chunk shared by 3 MMA passes.
#define PAD 40
#define TILE_E (128 * PAD)          // elements per tile
#define TILE_B (TILE_E * 2)         // 10240 bytes
#define STAGE_B (4 * TILE_B)        // 40960 bytes
#define SMEM_TOT (2 * STAGE_B)      // 81920 bytes

__global__ void __launch_bounds__(256) k_gemm(
    const __nv_bfloat16* __restrict__ Xhi, const __nv_bfloat16* __restrict__ Xlo,
    const __nv_bfloat16* __restrict__ Whi, const __nv_bfloat16* __restrict__ Wlo,
    __half* __restrict__ P, float* __restrict__ S)
{
    extern __shared__ char sm[];
    const int tid = threadIdx.x;
    const int wid = tid >> 5;
    const int wm = wid >> 1;          // 0..3
    const int wn = wid & 1;           // 0..1
    const int r0 = blockIdx.x * 128;
    const int n0 = blockIdx.y * 128;  // 0..511 in steps of 128

    wmma::fragment<wmma::accumulator, 16, 16, 16, float> acc[2][4];
    #pragma unroll
    for (int i = 0; i < 2; i++)
        #pragma unroll
        for (int j = 0; j < 4; j++)
            wmma::fill_fragment(acc[i][j], 0.0f);

    auto load_stage = [&](int s) {
        char* buf = sm + (s & 1) * STAGE_B;
        int kc = s * 32;
        #pragma unroll
        for (int u = 0; u < 2; u++) {
            int c = tid * 2 + u;          // 0..511 chunk within tile
            int row = c >> 2, kq = c & 3;
            uint32_t doff = (uint32_t)((row * PAD + kq * 8) * 2);
            // A tiles (0: hi, 1: lo) — node rows, OOB zero-filled
            int node = r0 + row;
            int nodeC = (node < NN) ? node : 0;
            int sz = (node < NN) ? 16 : 0;
            {
                const void* ga = Xhi + (size_t)nodeC * HH + kc + kq * 8;
                uint32_t da = (uint32_t)__cvta_generic_to_shared(buf + 0 * TILE_B + doff);
                asm volatile("cp.async.cg.shared.global [%0], [%1], 16, %2;" :: "r"(da), "l"(ga), "r"(sz) : "memory");
            }
            {
                const void* ga = Xlo + (size_t)nodeC * HH + kc + kq * 8;
                uint32_t da = (uint32_t)__cvta_generic_to_shared(buf + 1 * TILE_B + doff);
                asm volatile("cp.async.cg.shared.global [%0], [%1], 16, %2;" :: "r"(da), "l"(ga), "r"(sz) : "memory");
            }
            // B tiles (2: hi, 3: lo) — weight rows n0+row
            int nr = n0 + row;
            {
                const void* gb = Whi + (size_t)nr * HH + kc + kq * 8;
                uint32_t db = (uint32_t)__cvta_generic_to_shared(buf + 2 * TILE_B + doff);
                asm volatile("cp.async.cg.shared.global [%0], [%1], 16;" :: "r"(db), "l"(gb) : "memory");
            }
            {
                const void* gb = Wlo + (size_t)nr * HH + kc + kq * 8;
                uint32_t db = (uint32_t)__cvta_generic_to_shared(buf + 3 * TILE_B + doff);
                asm volatile("cp.async.cg.shared.global [%0], [%1], 16;" :: "r"(db), "l"(gb) : "memory");
            }
        }
        asm volatile("cp.async.commit_group;" ::: "memory");
    };

    load_stage(0);

    for (int s = 0; s < 8; s++) {
        asm volatile("cp.async.wait_group 0;" ::: "memory");
        __syncthreads();
        const __nv_bfloat16* buf = (const __nv_bfloat16*)(sm + (s & 1) * STAGE_B);
        if (s + 1 < 8) load_stage(s + 1);

        #pragma unroll
        for (int seg = 0; seg < 3; seg++) {
            const __nv_bfloat16* At = buf + ((seg == 1) ? 1 : 0) * TILE_E;
            const __nv_bfloat16* Bt = buf + (2 + ((seg == 2) ? 1 : 0)) * TILE_E;
            #pragma unroll
            for (int kk = 0; kk < 32; kk += 16) {
                wmma::fragment<wmma::matrix_a, 16, 16, 16, __nv_bfloat16, wmma::row_major> af[2];
                wmma::fragment<wmma::matrix_b, 16, 16, 16, __nv_bfloat16, wmma::col_major> bf[4];
                #pragma unroll
                for (int i = 0; i < 2; i++)
                    wmma::load_matrix_sync(af[i], At + (wm * 32 + i * 16) * PAD + kk, PAD);
                #pragma unroll
                for (int j = 0; j < 4; j++)
                    wmma::load_matrix_sync(bf[j], Bt + (wn * 64 + j * 16) * PAD + kk, PAD);
                #pragma unroll
                for (int i = 0; i < 2; i++)
                    #pragma unroll
                    for (int j = 0; j < 4; j++)
                        wmma::mma_sync(acc[i][j], af[i], bf[j], acc[i][j]);
            }
        }
    }

    __syncthreads();   // done reading tiles; smem reusable for staging

    if (n0 < 256) {
        // P block: stage fp32 in smem, convert to fp16 (coalesced 16B stores)
        float* stg = (float*)sm;
        #pragma unroll
        for (int i = 0; i < 2; i++)
            #pragma unroll
            for (int j = 0; j < 4; j++)
                wmma::store_matrix_sync(stg + (wm * 32 + i * 16) * 128 + (wn * 64 + j * 16),
                                        acc[i][j], 128, wmma::mem_row_major);
        __syncthreads();
        #pragma unroll
        for (int g = 0; g < 8; g++) {
            int gid = g * 256 + tid;      // 0..2047 groups of 8 elems
            int row = gid >> 4, c8 = (gid & 15) * 8;
            int node = r0 + row;
            if (node < NN) {
                const float* p = stg + row * 128 + c8;
                __half2 h0 = __floats2half2_rn(p[0], p[1]);
                __half2 h1 = __floats2half2_rn(p[2], p[3]);
                __half2 h2 = __floats2half2_rn(p[4], p[5]);
                __half2 h3 = __floats2half2_rn(p[6], p[7]);
                uint4 v;
                v.x = *(uint32_t*)&h0; v.y = *(uint32_t*)&h1;
                v.z = *(uint32_t*)&h2; v.w = *(uint32_t*)&h3;
                *(uint4*)(P + (size_t)node * HH + n0 + c8) = v;
            }
        }
    } else {
        // S block: store fp32 directly (NN % 16 == 0, tiles never straddle)
        #pragma unroll
        for (int i = 0; i < 2; i++) {
            int mrow = r0 + wm * 32 + i * 16;
            if (mrow < NN) {
                #pragma unroll
                for (int j = 0; j < 4; j++)
                    wmma::store_matrix_sync(S + (size_t)mrow * HH + (n0 - 256) + wn * 64 + j * 16,
                                            acc[i][j], HH, wmma::mem_row_major);
            }
        }
    }
}

// ---------------- fused aggregation epilogue: h = act(mean_agg(P) + S), + bf16 split ----------------
__global__ void k_agg_f(const __half* __restrict__ P, const float* __restrict__ S,
                        __nv_bfloat16* __restrict__ hhi, __nv_bfloat16* __restrict__ hlo,
                        float* __restrict__ hout, int sig) {
    int gwarp = (blockIdx.x * blockDim.x + threadIdx.x) >> 5;
    int lane  = threadIdx.x & 31;
    if (gwarp >= NN) return;
    int beg = g_rowptr[gwarp], end = g_rowptr[gwarp + 1];
    float a[8] = {0.f, 0.f, 0.f, 0.f, 0.f, 0.f, 0.f, 0.f};
    const uint4* Pb = (const uint4*)P;   // 32 uint4 per row
    for (int e = beg; e < end; e++) {
        uint4 v = __ldg(Pb + (size_t)g_col[e] * 32 + lane);
        const __half2* hp = (const __half2*)&v;
        float2 f0 = __half22float2(hp[0]);
        float2 f1 = __half22float2(hp[1]);
        float2 f2 = __half22float2(hp[2]);
        float2 f3 = __half22float2(hp[3]);
        a[0] += f0.x; a[1] += f0.y; a[2] += f1.x; a[3] += f1.y;
        a[4] += f2.x; a[5] += f2.y; a[6] += f3.x; a[7] += f3.y;
    }
    float inv = g_invdeg[gwarp];
    size_t base = (size_t)gwarp * HH + lane * 8;
    const float4* Sr = (const float4*)(S + base);
    float4 s0 = __ldg(Sr), s1 = __ldg(Sr + 1);
    float pre[8];
    pre[0] = a[0] * inv + s0.x; pre[1] = a[1] * inv + s0.y;
    pre[2] = a[2] * inv + s0.z; pre[3] = a[3] * inv + s0.w;
    pre[4] = a[4] * inv + s1.x; pre[5] = a[5] * inv + s1.y;
    pre[6] = a[6] * inv + s1.z; pre[7] = a[7] * inv + s1.w;
    if (sig) {
        #pragma unroll
        for (int k = 0; k < 8; k++)
            pre[k] = 1.0f / (1.0f + expf(-pre[k]));
    }
    split8(pre, hhi + base, hlo + base);
    if (hout) {
        float4 o0 = make_float4(pre[0], pre[1], pre[2], pre[3]);
        float4 o1 = make_float4(pre[4], pre[5], pre[6], pre[7]);
        *(float4*)(hout + base) = o0;
        *(float4*)(hout + base + 4) = o1;
    }
}

// ---------------- output projection ----------------
__global__ void k_out(const float* __restrict__ h, const float* __restrict__ w,
                      const float* __restrict__ b, float* __restrict__ out) {
    int gwarp = (blockIdx.x * blockDim.x + threadIdx.x) >> 5;
    int lane  = threadIdx.x & 31;
    if (gwarp >= NN) return;
    const float4* hr = (const float4*)(h + (size_t)gwarp * HH);
    const float4* wr = (const float4*)w;
    float4 h0 = __ldg(&hr[lane]),      w0 = __ldg(&wr[lane]);
    float4 h1 = __ldg(&hr[lane + 32]), w1 = __ldg(&wr[lane + 32]);
    float s = h0.x * w0.x + h0.y * w0.y + h0.z * w0.z + h0.w * w0.w
            + h1.x * w1.x + h1.y * w1.y + h1.z * w1.z + h1.w * w1.w;
    #pragma unroll
    for (int off = 16; off > 0; off >>= 1)
        s += __shfl_xor_sync(0xFFFFFFFF, s, off);
    if (lane == 0) out[gwarp] = s + b[0];
}

extern "C" void kernel_launch(void* const* d_in, const int* in_sizes, int n_in,
                              void* d_out, int out_size) {
    const float* x     = (const float*)d_in[0];
    const int*   ei    = (const int*)d_in[1];
    const float* WA_in = (const float*)d_in[2];
    const float* WB_in = (const float*)d_in[3];
    const float* A_st  = (const float*)d_in[4];
    const float* B_st  = (const float*)d_in[5];
    const float* W_out = (const float*)d_in[6];
    const float* b_out = (const float*)d_in[7];
    float*       out   = (float*)d_out;

    const int* src = ei;
    const int* dst = ei + EE;

    __nv_bfloat16 *x_hi, *x_lo, *h_hi, *h_lo, *wc_hi, *wc_lo;
    __half* P; float *S, *h3;
    cudaGetSymbolAddress((void**)&x_hi, g_x_hi);
    cudaGetSymbolAddress((void**)&x_lo, g_x_lo);
    cudaGetSymbolAddress((void**)&h_hi, g_h_hi);
    cudaGetSymbolAddress((void**)&h_lo, g_h_lo);
    cudaGetSymbolAddress((void**)&wc_hi, g_wcat_hi);
    cudaGetSymbolAddress((void**)&wc_lo, g_wcat_lo);
    cudaGetSymbolAddress((void**)&P, g_P);
    cudaGetSymbolAddress((void**)&S, g_S);
    cudaGetSymbolAddress((void**)&h3, g_h3);

    cudaFuncSetAttribute(k_gemm, cudaFuncAttributeMaxDynamicSharedMemorySize, SMEM_TOT);

    const size_t WSZ = (size_t)512 * HH;
    dim3 gGemm((NN + 127) / 128, 4);
    const int aggBlocks = (NN + 7) / 8;

    // #0..#4 — prep + start of CSR (GEMM0 at launch index 5 for ncu -s 5)
    dim3 gW((512 * HH + 255) / 256, 3);
    k_convert_w<<<gW, 256>>>(WA_in, WB_in, A_st, B_st);            // 0
    k_split_x<<<(NN * HH / 8 + 255) / 256, 256>>>(x);              // 1
    k_zero<<<(NN + 255) / 256, 256>>>();                           // 2
    k_count<<<(EE + 255) / 256, 256>>>(dst);                       // 3
    k_scan_blocks<<<NB_SCAN, 1024>>>();                            // 4

    // layer 0 GEMM: [P|S] = x @ [WA|WB]   (no CSR dependency)
    k_gemm<<<gGemm, 256, SMEM_TOT>>>(x_hi, x_lo, wc_hi, wc_lo, P, S);   // 5

    // finish CSR
    k_scan_sums<<<1, 64>>>();                                      // 6
    k_finalize<<<NB_SCAN, 1024>>>();                               // 7
    k_fill<<<(EE + 255) / 256, 256>>>(src, dst);                   // 8

    // layer 0 epilogue: h1 = mean_agg(P) + S (no sigmoid)
    k_agg_f<<<aggBlocks, 256>>>(P, S, h_hi, h_lo, nullptr, 0);     // 9

    // layer 1
    k_gemm<<<gGemm, 256, SMEM_TOT>>>(h_hi, h_lo, wc_hi + WSZ, wc_lo + WSZ, P, S);
    k_agg_f<<<aggBlocks, 256>>>(P, S, h_hi, h_lo, nullptr, 1);

    // layer 2
    k_gemm<<<gGemm, 256, SMEM_TOT>>>(h_hi, h_lo, wc_hi + 2 * WSZ, wc_lo + 2 * WSZ, P, S);
    k_agg_f<<<aggBlocks, 256>>>(P, S, h_hi, h_lo, h3, 1);

    // projection
    k_out<<<aggBlocks, 256>>>(h3, W_out, b_out, out);
}

// round 6
// speedup vs baseline: 2.5212x; 1.3865x over previous
#include <cuda_runtime.h>
#include <cuda_fp16.h>
#include <mma.h>
#include <cstdint>

using namespace nvcuda;

#define NN 50000
#define EE 800000
#define HH 256
#define NB_SCAN 49   // ceil(NN/1024)

// ---------------- scratch (device globals; no runtime allocation) ----------------
__device__ __half g_x_hi[(size_t)NN * HH];
__device__ __half g_x_lo[(size_t)NN * HH];
__device__ __half g_h_hi[(size_t)NN * HH];
__device__ __half g_h_lo[(size_t)NN * HH];
__device__ __half g_P[(size_t)NN * HH];
__device__ float  g_S[(size_t)NN * HH];
__device__ __half g_wcat[3 * 512 * HH];
__device__ float g_invdeg[NN];
__device__ int   g_deg[NN];
__device__ int   g_rowptr[NN + 1];
__device__ int   g_pos[NN];
__device__ int   g_col[EE];
__device__ int   g_bsum[NB_SCAN];

// ---------------- fp16 exact split helper ----------------
__device__ __forceinline__ void split8h(const float* v, __half* hi, __half* lo) {
    uint4 H, L;
    uint32_t* Hp = (uint32_t*)&H;
    uint32_t* Lp = (uint32_t*)&L;
    #pragma unroll
    for (int p = 0; p < 4; p++) {
        __half h0 = __float2half_rn(v[p * 2 + 0]);
        __half h1 = __float2half_rn(v[p * 2 + 1]);
        __half l0 = __float2half_rn(v[p * 2 + 0] - __half2float(h0));
        __half l1 = __float2half_rn(v[p * 2 + 1] - __half2float(h1));
        Hp[p] = ((uint32_t)__half_as_ushort(h1) << 16) | __half_as_ushort(h0);
        Lp[p] = ((uint32_t)__half_as_ushort(l1) << 16) | __half_as_ushort(l0);
    }
    *(uint4*)hi = H;
    *(uint4*)lo = L;
}

// ---------------- CSR construction ----------------
__global__ void k_zero() {
    int i = blockIdx.x * blockDim.x + threadIdx.x;
    if (i < NN) { g_deg[i] = 0; g_pos[i] = 0; }
}

__global__ void k_count(const int* __restrict__ dst) {
    int e = blockIdx.x * blockDim.x + threadIdx.x;
    if (e < EE) atomicAdd(&g_deg[dst[e]], 1);
}

__global__ void k_scan_blocks() {
    __shared__ int s[1024];
    int t = threadIdx.x;
    int i = blockIdx.x * 1024 + t;
    int v = (i < NN) ? g_deg[i] : 0;
    s[t] = v;
    __syncthreads();
    #pragma unroll
    for (int off = 1; off < 1024; off <<= 1) {
        int add = (t >= off) ? s[t - off] : 0;
        __syncthreads();
        s[t] += add;
        __syncthreads();
    }
    if (i < NN) g_rowptr[i] = s[t] - v;
    if (t == 1023) g_bsum[blockIdx.x] = s[t];
}

__global__ void k_scan_sums() {
    __shared__ int s[64];
    int t = threadIdx.x;
    int v = (t < NB_SCAN) ? g_bsum[t] : 0;
    s[t] = v;
    __syncthreads();
    #pragma unroll
    for (int off = 1; off < 64; off <<= 1) {
        int a = (t >= off) ? s[t - off] : 0;
        __syncthreads();
        s[t] += a;
        __syncthreads();
    }
    if (t < NB_SCAN) g_bsum[t] = s[t] - v;
}

__global__ void k_finalize() {
    int t = threadIdx.x;
    int i = blockIdx.x * 1024 + t;
    if (i < NN) {
        g_rowptr[i] += g_bsum[blockIdx.x];
        int d = g_deg[i];
        g_invdeg[i] = 1.0f / (float)(d > 0 ? d : 1);
    }
    if (i == 0) g_rowptr[NN] = EE;
}

__global__ void k_fill(const int* __restrict__ src, const int* __restrict__ dst) {
    int e = blockIdx.x * blockDim.x + threadIdx.x;
    if (e < EE) {
        int d = dst[e];
        int p = atomicAdd(&g_pos[d], 1);
        g_col[g_rowptr[d] + p] = src[e];
    }
}

// ---------------- weight conversion: concat [Wagg|Wself], transpose to [512,256], fp16 ----------------
__global__ void k_convert_w(const float* __restrict__ WA, const float* __restrict__ WB,
                            const float* __restrict__ Ast, const float* __restrict__ Bst) {
    int l = blockIdx.y;
    const float* Wagg  = (l == 0) ? WA : (l == 1) ? Ast : (Ast + HH * HH);
    const float* Wself = (l == 0) ? WB : (l == 1) ? Bst : (Bst + HH * HH);
    int idx = blockIdx.x * blockDim.x + threadIdx.x;   // 0 .. 512*256-1
    if (idx >= 512 * HH) return;
    int n = idx >> 8, k = idx & 255;
    const float* srcW = (n < 256) ? Wagg : Wself;
    float v = __ldg(srcW + k * HH + (n & 255));
    g_wcat[(size_t)l * 512 * HH + idx] = __float2half_rn(v);
}

// ---------------- input split ----------------
__global__ void k_split_x(const float* __restrict__ x) {
    int i = blockIdx.x * blockDim.x + threadIdx.x;   // group of 8 floats
    if (i >= NN * HH / 8) return;
    float v[8];
    const float4* p = (const float4*)x + i * 2;
    float4 a = __ldg(p), b = __ldg(p + 1);
    v[0] = a.x; v[1] = a.y; v[2] = a.z; v[3] = a.w;
    v[4] = b.x; v[5] = b.y; v[6] = b.z; v[7] = b.w;
    split8h(v, g_x_hi + (size_t)i * 8, g_x_lo + (size_t)i * 8);
}

// ---------------- wmma fp16 2-pass GEMM: [P|S] = (Xhi + Xlo) @ Wcat ----------------
#define PAD 40
#define TILE_E (128 * PAD)          // elements per tile
#define TILE_B (TILE_E * 2)         // 10240 bytes
#define STAGE_B (3 * TILE_B)        // 30720 bytes (A_hi, A_lo, B)
// NOTE: epilogue stages a 128x128 fp32 tile (65536 B) in the same dynamic smem;
// total must cover max(2*STAGE_B, 65536). Round 5 bug: this was 61440.
#define SMEM_TOT 65536

__global__ void __launch_bounds__(256) k_gemm(
    const __half* __restrict__ Xhi, const __half* __restrict__ Xlo,
    const __half* __restrict__ W,
    __half* __restrict__ P, float* __restrict__ S)
{
    extern __shared__ char sm[];
    const int tid = threadIdx.x;
    const int wid = tid >> 5;
    const int wm = wid >> 1;          // 0..3
    const int wn = wid & 1;           // 0..1
    const int r0 = blockIdx.x * 128;
    const int n0 = blockIdx.y * 128;  // 0..511 in steps of 128

    wmma::fragment<wmma::accumulator, 16, 16, 16, float> acc[2][4];
    #pragma unroll
    for (int i = 0; i < 2; i++)
        #pragma unroll
        for (int j = 0; j < 4; j++)
            wmma::fill_fragment(acc[i][j], 0.0f);

    auto load_stage = [&](int s) {
        char* buf = sm + (s & 1) * STAGE_B;
        int kc = s * 32;
        #pragma unroll
        for (int u = 0; u < 2; u++) {
            int c = tid * 2 + u;          // 0..511 chunk within tile
            int row = c >> 2, kq = c & 3;
            uint32_t doff = (uint32_t)((row * PAD + kq * 8) * 2);
            int node = r0 + row;
            int nodeC = (node < NN) ? node : 0;
            int sz = (node < NN) ? 16 : 0;
            {
                const void* ga = Xhi + (size_t)nodeC * HH + kc + kq * 8;
                uint32_t da = (uint32_t)__cvta_generic_to_shared(buf + 0 * TILE_B + doff);
                asm volatile("cp.async.cg.shared.global [%0], [%1], 16, %2;" :: "r"(da), "l"(ga), "r"(sz) : "memory");
            }
            {
                const void* ga = Xlo + (size_t)nodeC * HH + kc + kq * 8;
                uint32_t da = (uint32_t)__cvta_generic_to_shared(buf + 1 * TILE_B + doff);
                asm volatile("cp.async.cg.shared.global [%0], [%1], 16, %2;" :: "r"(da), "l"(ga), "r"(sz) : "memory");
            }
            {
                const void* gb = W + (size_t)(n0 + row) * HH + kc + kq * 8;
                uint32_t db = (uint32_t)__cvta_generic_to_shared(buf + 2 * TILE_B + doff);
                asm volatile("cp.async.cg.shared.global [%0], [%1], 16;" :: "r"(db), "l"(gb) : "memory");
            }
        }
        asm volatile("cp.async.commit_group;" ::: "memory");
    };

    load_stage(0);

    for (int s = 0; s < 8; s++) {
        asm volatile("cp.async.wait_group 0;" ::: "memory");
        __syncthreads();
        const __half* buf = (const __half*)(sm + (s & 1) * STAGE_B);
        if (s + 1 < 8) load_stage(s + 1);

        const __half* Ahi = buf;
        const __half* Alo = buf + TILE_E;
        const __half* Bt  = buf + 2 * TILE_E;

        #pragma unroll
        for (int kk = 0; kk < 32; kk += 16) {
            wmma::fragment<wmma::matrix_b, 16, 16, 16, __half, wmma::col_major> bf[4];
            #pragma unroll
            for (int j = 0; j < 4; j++)
                wmma::load_matrix_sync(bf[j], Bt + (wn * 64 + j * 16) * PAD + kk, PAD);

            wmma::fragment<wmma::matrix_a, 16, 16, 16, __half, wmma::row_major> af[2];
            #pragma unroll
            for (int i = 0; i < 2; i++)
                wmma::load_matrix_sync(af[i], Ahi + (wm * 32 + i * 16) * PAD + kk, PAD);
            #pragma unroll
            for (int i = 0; i < 2; i++)
                #pragma unroll
                for (int j = 0; j < 4; j++)
                    wmma::mma_sync(acc[i][j], af[i], bf[j], acc[i][j]);

            #pragma unroll
            for (int i = 0; i < 2; i++)
                wmma::load_matrix_sync(af[i], Alo + (wm * 32 + i * 16) * PAD + kk, PAD);
            #pragma unroll
            for (int i = 0; i < 2; i++)
                #pragma unroll
                for (int j = 0; j < 4; j++)
                    wmma::mma_sync(acc[i][j], af[i], bf[j], acc[i][j]);
        }
    }

    __syncthreads();   // done reading tiles; smem reusable for staging

    if (n0 < 256) {
        // P block: stage fp32 in smem (65536 B), convert to fp16 (coalesced 16B stores)
        float* stg = (float*)sm;
        #pragma unroll
        for (int i = 0; i < 2; i++)
            #pragma unroll
            for (int j = 0; j < 4; j++)
                wmma::store_matrix_sync(stg + (wm * 32 + i * 16) * 128 + (wn * 64 + j * 16),
                                        acc[i][j], 128, wmma::mem_row_major);
        __syncthreads();
        #pragma unroll
        for (int g = 0; g < 8; g++) {
            int gid = g * 256 + tid;      // 0..2047 groups of 8 elems
            int row = gid >> 4, c8 = (gid & 15) * 8;
            int node = r0 + row;
            if (node < NN) {
                const float* p = stg + row * 128 + c8;
                __half2 h0 = __floats2half2_rn(p[0], p[1]);
                __half2 h1 = __floats2half2_rn(p[2], p[3]);
                __half2 h2 = __floats2half2_rn(p[4], p[5]);
                __half2 h3 = __floats2half2_rn(p[6], p[7]);
                uint4 v;
                v.x = *(uint32_t*)&h0; v.y = *(uint32_t*)&h1;
                v.z = *(uint32_t*)&h2; v.w = *(uint32_t*)&h3;
                *(uint4*)(P + (size_t)node * HH + n0 + c8) = v;
            }
        }
    } else {
        // S block: store fp32 directly (16-row tiles never straddle NN boundary)
        #pragma unroll
        for (int i = 0; i < 2; i++) {
            int mrow = r0 + wm * 32 + i * 16;
            if (mrow < NN) {
                #pragma unroll
                for (int j = 0; j < 4; j++)
                    wmma::store_matrix_sync(S + (size_t)mrow * HH + (n0 - 256) + wn * 64 + j * 16,
                                            acc[i][j], HH, wmma::mem_row_major);
            }
        }
    }
}

// ---------------- fused aggregation epilogue ----------------
// h = act(mean_agg(P) + S); either fp16 hi/lo split stores (next layer) or
// fused output projection (final layer).
__global__ void k_agg_f(const __half* __restrict__ P, const float* __restrict__ S,
                        __half* __restrict__ hhi, __half* __restrict__ hlo, int sig,
                        const float* __restrict__ Wout, const float* __restrict__ bout,
                        float* __restrict__ out) {
    int gwarp = (blockIdx.x * blockDim.x + threadIdx.x) >> 5;
    int lane  = threadIdx.x & 31;
    if (gwarp >= NN) return;
    int beg = g_rowptr[gwarp], end = g_rowptr[gwarp + 1];
    float a[8] = {0.f, 0.f, 0.f, 0.f, 0.f, 0.f, 0.f, 0.f};
    const uint4* Pb = (const uint4*)P;   // 32 uint4 per row
    for (int e = beg; e < end; e++) {
        uint4 v = __ldg(Pb + (size_t)g_col[e] * 32 + lane);
        const __half2* hp = (const __half2*)&v;
        float2 f0 = __half22float2(hp[0]);
        float2 f1 = __half22float2(hp[1]);
        float2 f2 = __half22float2(hp[2]);
        float2 f3 = __half22float2(hp[3]);
        a[0] += f0.x; a[1] += f0.y; a[2] += f1.x; a[3] += f1.y;
        a[4] += f2.x; a[5] += f2.y; a[6] += f3.x; a[7] += f3.y;
    }
    float inv = g_invdeg[gwarp];
    size_t base = (size_t)gwarp * HH + lane * 8;
    const float4* Sr = (const float4*)(S + base);
    float4 s0 = __ldg(Sr), s1 = __ldg(Sr + 1);
    float pre[8];
    pre[0] = a[0] * inv + s0.x; pre[1] = a[1] * inv + s0.y;
    pre[2] = a[2] * inv + s0.z; pre[3] = a[3] * inv + s0.w;
    pre[4] = a[4] * inv + s1.x; pre[5] = a[5] * inv + s1.y;
    pre[6] = a[6] * inv + s1.z; pre[7] = a[7] * inv + s1.w;
    if (sig) {
        #pragma unroll
        for (int k = 0; k < 8; k++)
            pre[k] = 1.0f / (1.0f + expf(-pre[k]));
    }
    if (out) {
        // final layer: fused h @ W_out + b
        const float4* wr = (const float4*)(Wout + lane * 8);
        float4 w0 = __ldg(wr), w1 = __ldg(wr + 1);
        float s = pre[0] * w0.x + pre[1] * w0.y + pre[2] * w0.z + pre[3] * w0.w
                + pre[4] * w1.x + pre[5] * w1.y + pre[6] * w1.z + pre[7] * w1.w;
        #pragma unroll
        for (int off = 16; off > 0; off >>= 1)
            s += __shfl_xor_sync(0xFFFFFFFF, s, off);
        if (lane == 0) out[gwarp] = s + bout[0];
    } else {
        split8h(pre, hhi + base, hlo + base);
    }
}

extern "C" void kernel_launch(void* const* d_in, const int* in_sizes, int n_in,
                              void* d_out, int out_size) {
    const float* x     = (const float*)d_in[0];
    const int*   ei    = (const int*)d_in[1];
    const float* WA_in = (const float*)d_in[2];
    const float* WB_in = (const float*)d_in[3];
    const float* A_st  = (const float*)d_in[4];
    const float* B_st  = (const float*)d_in[5];
    const float* W_out = (const float*)d_in[6];
    const float* b_out = (const float*)d_in[7];
    float*       out   = (float*)d_out;

    const int* src = ei;
    const int* dst = ei + EE;

    __half *x_hi, *x_lo, *h_hi, *h_lo, *wc, *P;
    float *S;
    cudaGetSymbolAddress((void**)&x_hi, g_x_hi);
    cudaGetSymbolAddress((void**)&x_lo, g_x_lo);
    cudaGetSymbolAddress((void**)&h_hi, g_h_hi);
    cudaGetSymbolAddress((void**)&h_lo, g_h_lo);
    cudaGetSymbolAddress((void**)&wc, g_wcat);
    cudaGetSymbolAddress((void**)&P, g_P);
    cudaGetSymbolAddress((void**)&S, g_S);

    cudaFuncSetAttribute(k_gemm, cudaFuncAttributeMaxDynamicSharedMemorySize, SMEM_TOT);

    const size_t WSZ = (size_t)512 * HH;
    dim3 gGemm((NN + 127) / 128, 4);
    const int aggBlocks = (NN + 7) / 8;

    // #0..#4 — prep + start of CSR (GEMM0 at launch index 5 for ncu -s 5)
    dim3 gW((512 * HH + 255) / 256, 3);
    k_convert_w<<<gW, 256>>>(WA_in, WB_in, A_st, B_st);            // 0
    k_split_x<<<(NN * HH / 8 + 255) / 256, 256>>>(x);              // 1
    k_zero<<<(NN + 255) / 256, 256>>>();                           // 2
    k_count<<<(EE + 255) / 256, 256>>>(dst);                       // 3
    k_scan_blocks<<<NB_SCAN, 1024>>>();                            // 4

    // layer 0 GEMM: [P|S] = x @ [WA|WB]   (no CSR dependency)
    k_gemm<<<gGemm, 256, SMEM_TOT>>>(x_hi, x_lo, wc, P, S);        // 5

    // finish CSR
    k_scan_sums<<<1, 64>>>();                                      // 6
    k_finalize<<<NB_SCAN, 1024>>>();                               // 7
    k_fill<<<(EE + 255) / 256, 256>>>(src, dst);                   // 8

    // layer 0 epilogue: h1 = mean_agg(P) + S (no sigmoid)
    k_agg_f<<<aggBlocks, 256>>>(P, S, h_hi, h_lo, 0, nullptr, nullptr, nullptr);  // 9

    // layer 1
    k_gemm<<<gGemm, 256, SMEM_TOT>>>(h_hi, h_lo, wc + WSZ, P, S);
    k_agg_f<<<aggBlocks, 256>>>(P, S, h_hi, h_lo, 1, nullptr, nullptr, nullptr);

    // layer 2 + fused projection
    k_gemm<<<gGemm, 256, SMEM_TOT>>>(h_hi, h_lo, wc + 2 * WSZ, P, S);
    k_agg_f<<<aggBlocks, 256>>>(P, S, nullptr, nullptr, 1, W_out, b_out, out);
}

// round 7
// speedup vs baseline: 3.1561x; 1.2518x over previous
#include <cuda_runtime.h>
#include <cuda_fp16.h>
#include <mma.h>
#include <cstdint>

using namespace nvcuda;

#define NN 50000
#define EE 800000
#define HH 256
#define NB_SCAN 49   // ceil(NN/1024)

// ---------------- scratch (device globals; no runtime allocation) ----------------
__device__ __half g_x[(size_t)NN * HH];
__device__ __half g_h[(size_t)NN * HH];
__device__ __half g_P[(size_t)NN * HH];
__device__ float  g_S[(size_t)NN * HH];
__device__ __half g_wcat[3 * 512 * HH];
__device__ float g_invdeg[NN];
__device__ int   g_deg[NN];
__device__ int   g_rowptr[NN + 1];
__device__ int   g_pos[NN];
__device__ int   g_col[EE];
__device__ int   g_bsum[NB_SCAN];

// ---------------- CSR construction ----------------
__global__ void k_zero() {
    int i = blockIdx.x * blockDim.x + threadIdx.x;
    if (i < NN) { g_deg[i] = 0; g_pos[i] = 0; }
}

__global__ void k_count(const int* __restrict__ dst) {
    int e = blockIdx.x * blockDim.x + threadIdx.x;
    if (e < EE) atomicAdd(&g_deg[dst[e]], 1);
}

__global__ void k_scan_blocks() {
    __shared__ int s[1024];
    int t = threadIdx.x;
    int i = blockIdx.x * 1024 + t;
    int v = (i < NN) ? g_deg[i] : 0;
    s[t] = v;
    __syncthreads();
    #pragma unroll
    for (int off = 1; off < 1024; off <<= 1) {
        int add = (t >= off) ? s[t - off] : 0;
        __syncthreads();
        s[t] += add;
        __syncthreads();
    }
    if (i < NN) g_rowptr[i] = s[t] - v;
    if (t == 1023) g_bsum[blockIdx.x] = s[t];
}

__global__ void k_scan_sums() {
    __shared__ int s[64];
    int t = threadIdx.x;
    int v = (t < NB_SCAN) ? g_bsum[t] : 0;
    s[t] = v;
    __syncthreads();
    #pragma unroll
    for (int off = 1; off < 64; off <<= 1) {
        int a = (t >= off) ? s[t - off] : 0;
        __syncthreads();
        s[t] += a;
        __syncthreads();
    }
    if (t < NB_SCAN) g_bsum[t] = s[t] - v;
}

__global__ void k_finalize() {
    int t = threadIdx.x;
    int i = blockIdx.x * 1024 + t;
    if (i < NN) {
        g_rowptr[i] += g_bsum[blockIdx.x];
        int d = g_deg[i];
        g_invdeg[i] = 1.0f / (float)(d > 0 ? d : 1);
    }
    if (i == 0) g_rowptr[NN] = EE;
}

__global__ void k_fill(const int* __restrict__ src, const int* __restrict__ dst) {
    int e = blockIdx.x * blockDim.x + threadIdx.x;
    if (e < EE) {
        int d = dst[e];
        int p = atomicAdd(&g_pos[d], 1);
        g_col[g_rowptr[d] + p] = src[e];
    }
}

// ---------------- weight conversion: concat [Wagg|Wself], transpose to [512,256], fp16 ----------------
__global__ void k_convert_w(const float* __restrict__ WA, const float* __restrict__ WB,
                            const float* __restrict__ Ast, const float* __restrict__ Bst) {
    int l = blockIdx.y;
    const float* Wagg  = (l == 0) ? WA : (l == 1) ? Ast : (Ast + HH * HH);
    const float* Wself = (l == 0) ? WB : (l == 1) ? Bst : (Bst + HH * HH);
    int idx = blockIdx.x * blockDim.x + threadIdx.x;   // 0 .. 512*256-1
    if (idx >= 512 * HH) return;
    int n = idx >> 8, k = idx & 255;
    const float* srcW = (n < 256) ? Wagg : Wself;
    float v = __ldg(srcW + k * HH + (n & 255));
    g_wcat[(size_t)l * 512 * HH + idx] = __float2half_rn(v);
}

// ---------------- input conversion fp32 -> fp16 ----------------
__global__ void k_convert_x(const float* __restrict__ x) {
    int i = blockIdx.x * blockDim.x + threadIdx.x;   // group of 8 floats
    if (i >= NN * HH / 8) return;
    const float4* p = (const float4*)x + i * 2;
    float4 a = __ldg(p), b = __ldg(p + 1);
    __half2 h0 = __floats2half2_rn(a.x, a.y);
    __half2 h1 = __floats2half2_rn(a.z, a.w);
    __half2 h2 = __floats2half2_rn(b.x, b.y);
    __half2 h3 = __floats2half2_rn(b.z, b.w);
    uint4 v;
    v.x = *(uint32_t*)&h0; v.y = *(uint32_t*)&h1;
    v.z = *(uint32_t*)&h2; v.w = *(uint32_t*)&h3;
    *(uint4*)(g_x + (size_t)i * 8) = v;
}

// ---------------- wmma fp16 GEMM: [P|S] = X @ Wcat ----------------
#define PAD 40
#define TILE_E (128 * PAD)          // elements per tile
#define TILE_B (TILE_E * 2)         // 10240 bytes
#define STAGE_B (2 * TILE_B)        // 20480 bytes (A, B)
// Epilogue stages a 128x128 fp32 tile (65536 B) in the same dynamic smem.
#define SMEM_TOT 65536

__global__ void __launch_bounds__(256) k_gemm(
    const __half* __restrict__ X, const __half* __restrict__ W,
    __half* __restrict__ P, float* __restrict__ S)
{
    extern __shared__ char sm[];
    const int tid = threadIdx.x;
    const int wid = tid >> 5;
    const int wm = wid >> 1;          // 0..3
    const int wn = wid & 1;           // 0..1
    const int r0 = blockIdx.x * 128;
    const int n0 = blockIdx.y * 128;  // 0..511 in steps of 128

    wmma::fragment<wmma::accumulator, 16, 16, 16, float> acc[2][4];
    #pragma unroll
    for (int i = 0; i < 2; i++)
        #pragma unroll
        for (int j = 0; j < 4; j++)
            wmma::fill_fragment(acc[i][j], 0.0f);

    auto load_stage = [&](int s) {
        char* buf = sm + (s & 1) * STAGE_B;
        int kc = s * 32;
        #pragma unroll
        for (int u = 0; u < 2; u++) {
            int c = tid * 2 + u;          // 0..511 chunk within tile
            int row = c >> 2, kq = c & 3;
            uint32_t doff = (uint32_t)((row * PAD + kq * 8) * 2);
            int node = r0 + row;
            int nodeC = (node < NN) ? node : 0;
            int sz = (node < NN) ? 16 : 0;
            {
                const void* ga = X + (size_t)nodeC * HH + kc + kq * 8;
                uint32_t da = (uint32_t)__cvta_generic_to_shared(buf + 0 * TILE_B + doff);
                asm volatile("cp.async.cg.shared.global [%0], [%1], 16, %2;" :: "r"(da), "l"(ga), "r"(sz) : "memory");
            }
            {
                const void* gb = W + (size_t)(n0 + row) * HH + kc + kq * 8;
                uint32_t db = (uint32_t)__cvta_generic_to_shared(buf + 1 * TILE_B + doff);
                asm volatile("cp.async.cg.shared.global [%0], [%1], 16;" :: "r"(db), "l"(gb) : "memory");
            }
        }
        asm volatile("cp.async.commit_group;" ::: "memory");
    };

    load_stage(0);

    for (int s = 0; s < 8; s++) {
        asm volatile("cp.async.wait_group 0;" ::: "memory");
        __syncthreads();
        const __half* buf = (const __half*)(sm + (s & 1) * STAGE_B);
        if (s + 1 < 8) load_stage(s + 1);

        const __half* At = buf;
        const __half* Bt = buf + TILE_E;

        #pragma unroll
        for (int kk = 0; kk < 32; kk += 16) {
            wmma::fragment<wmma::matrix_b, 16, 16, 16, __half, wmma::col_major> bf[4];
            #pragma unroll
            for (int j = 0; j < 4; j++)
                wmma::load_matrix_sync(bf[j], Bt + (wn * 64 + j * 16) * PAD + kk, PAD);

            wmma::fragment<wmma::matrix_a, 16, 16, 16, __half, wmma::row_major> af[2];
            #pragma unroll
            for (int i = 0; i < 2; i++)
                wmma::load_matrix_sync(af[i], At + (wm * 32 + i * 16) * PAD + kk, PAD);
            #pragma unroll
            for (int i = 0; i < 2; i++)
                #pragma unroll
                for (int j = 0; j < 4; j++)
                    wmma::mma_sync(acc[i][j], af[i], bf[j], acc[i][j]);
        }
    }

    __syncthreads();   // done reading tiles; smem reusable for staging

    if (n0 < 256) {
        // P block: stage fp32 in smem (65536 B), convert to fp16 (coalesced 16B stores)
        float* stg = (float*)sm;
        #pragma unroll
        for (int i = 0; i < 2; i++)
            #pragma unroll
            for (int j = 0; j < 4; j++)
                wmma::store_matrix_sync(stg + (wm * 32 + i * 16) * 128 + (wn * 64 + j * 16),
                                        acc[i][j], 128, wmma::mem_row_major);
        __syncthreads();
        #pragma unroll
        for (int g = 0; g < 8; g++) {
            int gid = g * 256 + tid;      // 0..2047 groups of 8 elems
            int row = gid >> 4, c8 = (gid & 15) * 8;
            int node = r0 + row;
            if (node < NN) {
                const float* p = stg + row * 128 + c8;
                __half2 h0 = __floats2half2_rn(p[0], p[1]);
                __half2 h1 = __floats2half2_rn(p[2], p[3]);
                __half2 h2 = __floats2half2_rn(p[4], p[5]);
                __half2 h3 = __floats2half2_rn(p[6], p[7]);
                uint4 v;
                v.x = *(uint32_t*)&h0; v.y = *(uint32_t*)&h1;
                v.z = *(uint32_t*)&h2; v.w = *(uint32_t*)&h3;
                *(uint4*)(P + (size_t)node * HH + n0 + c8) = v;
            }
        }
    } else {
        // S block: store fp32 directly (16-row tiles never straddle NN boundary)
        #pragma unroll
        for (int i = 0; i < 2; i++) {
            int mrow = r0 + wm * 32 + i * 16;
            if (mrow < NN) {
                #pragma unroll
                for (int j = 0; j < 4; j++)
                    wmma::store_matrix_sync(S + (size_t)mrow * HH + (n0 - 256) + wn * 64 + j * 16,
                                            acc[i][j], HH, wmma::mem_row_major);
            }
        }
    }
}

// ---------------- fused aggregation epilogue ----------------
// h = act(mean_agg(P) + S); fp16 h store (next layer) or fused projection (final).
__global__ void k_agg_f(const __half* __restrict__ P, const float* __restrict__ S,
                        __half* __restrict__ hout, int sig,
                        const float* __restrict__ Wout, const float* __restrict__ bout,
                        float* __restrict__ out) {
    int gwarp = (blockIdx.x * blockDim.x + threadIdx.x) >> 5;
    int lane  = threadIdx.x & 31;
    if (gwarp >= NN) return;
    int beg = g_rowptr[gwarp], end = g_rowptr[gwarp + 1];
    float a[8] = {0.f, 0.f, 0.f, 0.f, 0.f, 0.f, 0.f, 0.f};
    const uint4* Pb = (const uint4*)P;   // 32 uint4 per row
    for (int e = beg; e < end; e++) {
        uint4 v = __ldg(Pb + (size_t)g_col[e] * 32 + lane);
        const __half2* hp = (const __half2*)&v;
        float2 f0 = __half22float2(hp[0]);
        float2 f1 = __half22float2(hp[1]);
        float2 f2 = __half22float2(hp[2]);
        float2 f3 = __half22float2(hp[3]);
        a[0] += f0.x; a[1] += f0.y; a[2] += f1.x; a[3] += f1.y;
        a[4] += f2.x; a[5] += f2.y; a[6] += f3.x; a[7] += f3.y;
    }
    float inv = g_invdeg[gwarp];
    size_t base = (size_t)gwarp * HH + lane * 8;
    const float4* Sr = (const float4*)(S + base);
    float4 s0 = __ldg(Sr), s1 = __ldg(Sr + 1);
    float pre[8];
    pre[0] = a[0] * inv + s0.x; pre[1] = a[1] * inv + s0.y;
    pre[2] = a[2] * inv + s0.z; pre[3] = a[3] * inv + s0.w;
    pre[4] = a[4] * inv + s1.x; pre[5] = a[5] * inv + s1.y;
    pre[6] = a[6] * inv + s1.z; pre[7] = a[7] * inv + s1.w;
    if (sig) {
        #pragma unroll
        for (int k = 0; k < 8; k++)
            pre[k] = 1.0f / (1.0f + expf(-pre[k]));
    }
    if (out) {
        // final layer: fused h @ W_out + b
        const float4* wr = (const float4*)(Wout + lane * 8);
        float4 w0 = __ldg(wr), w1 = __ldg(wr + 1);
        float s = pre[0] * w0.x + pre[1] * w0.y + pre[2] * w0.z + pre[3] * w0.w
                + pre[4] * w1.x + pre[5] * w1.y + pre[6] * w1.z + pre[7] * w1.w;
        #pragma unroll
        for (int off = 16; off > 0; off >>= 1)
            s += __shfl_xor_sync(0xFFFFFFFF, s, off);
        if (lane == 0) out[gwarp] = s + bout[0];
    } else {
        __half2 h0 = __floats2half2_rn(pre[0], pre[1]);
        __half2 h1 = __floats2half2_rn(pre[2], pre[3]);
        __half2 h2 = __floats2half2_rn(pre[4], pre[5]);
        __half2 h3 = __floats2half2_rn(pre[6], pre[7]);
        uint4 v;
        v.x = *(uint32_t*)&h0; v.y = *(uint32_t*)&h1;
        v.z = *(uint32_t*)&h2; v.w = *(uint32_t*)&h3;
        *(uint4*)(hout + base) = v;
    }
}

extern "C" void kernel_launch(void* const* d_in, const int* in_sizes, int n_in,
                              void* d_out, int out_size) {
    const float* x     = (const float*)d_in[0];
    const int*   ei    = (const int*)d_in[1];
    const float* WA_in = (const float*)d_in[2];
    const float* WB_in = (const float*)d_in[3];
    const float* A_st  = (const float*)d_in[4];
    const float* B_st  = (const float*)d_in[5];
    const float* W_out = (const float*)d_in[6];
    const float* b_out = (const float*)d_in[7];
    float*       out   = (float*)d_out;

    const int* src = ei;
    const int* dst = ei + EE;

    __half *xh, *h, *wc, *P;
    float *S;
    cudaGetSymbolAddress((void**)&xh, g_x);
    cudaGetSymbolAddress((void**)&h, g_h);
    cudaGetSymbolAddress((void**)&wc, g_wcat);
    cudaGetSymbolAddress((void**)&P, g_P);
    cudaGetSymbolAddress((void**)&S, g_S);

    cudaFuncSetAttribute(k_gemm, cudaFuncAttributeMaxDynamicSharedMemorySize, SMEM_TOT);

    const size_t WSZ = (size_t)512 * HH;
    dim3 gGemm((NN + 127) / 128, 4);
    const int aggBlocks = (NN + 7) / 8;

    // #0..#4 — prep + start of CSR (GEMM0 at launch index 5 for ncu -s 5)
    dim3 gW((512 * HH + 255) / 256, 3);
    k_convert_w<<<gW, 256>>>(WA_in, WB_in, A_st, B_st);            // 0
    k_convert_x<<<(NN * HH / 8 + 255) / 256, 256>>>(x);            // 1
    k_zero<<<(NN + 255) / 256, 256>>>();                           // 2
    k_count<<<(EE + 255) / 256, 256>>>(dst);                       // 3
    k_scan_blocks<<<NB_SCAN, 1024>>>();                            // 4

    // layer 0 GEMM: [P|S] = x @ [WA|WB]   (no CSR dependency)
    k_gemm<<<gGemm, 256, SMEM_TOT>>>(xh, wc, P, S);                // 5

    // finish CSR
    k_scan_sums<<<1, 64>>>();                                      // 6
    k_finalize<<<NB_SCAN, 1024>>>();                               // 7
    k_fill<<<(EE + 255) / 256, 256>>>(src, dst);                   // 8

    // layer 0 epilogue: h1 = mean_agg(P) + S (no sigmoid)
    k_agg_f<<<aggBlocks, 256>>>(P, S, h, 0, nullptr, nullptr, nullptr);  // 9

    // layer 1
    k_gemm<<<gGemm, 256, SMEM_TOT>>>(h, wc + WSZ, P, S);
    k_agg_f<<<aggBlocks, 256>>>(P, S, h, 1, nullptr, nullptr, nullptr);

    // layer 2 + fused projection
    k_gemm<<<gGemm, 256, SMEM_TOT>>>(h, wc + 2 * WSZ, P, S);
    k_agg_f<<<aggBlocks, 256>>>(P, S, nullptr, 1, W_out, b_out, out);
}